// round 1
// baseline (speedup 1.0000x reference)
#include <cuda_runtime.h>
#include <math.h>
#include <stdint.h>

#define BATCH 32
#define DIMD  512
#define MSZ   1024
#define NSZ   1024
#define SINK_ITERS 5
#define MSPLIT 8

// ---------------- device scratch (static: no allocations) ----------------
__device__ float g_K[(size_t)BATCH * MSZ * NSZ];       // 134 MB kernel matrix
__device__ float g_n1[BATCH * MSZ];
__device__ float g_n2[BATCH * NSZ];
__device__ float g_u[BATCH * MSZ];
__device__ float g_v[BATCH * NSZ];
__device__ float g_vpart[MSPLIT * BATCH * NSZ];
__device__ float g_rowS[BATCH * MSZ];
__device__ float g_wref[BATCH * MSZ * 3];
__device__ float g_cov[BATCH * 9];
__device__ float g_ca[BATCH * 3];
__device__ float g_cb[BATCH * 3];

// ---------------- helpers ----------------
__device__ __forceinline__ float blockReduceB(float v, volatile float* sred) {
    int lane = threadIdx.x & 31;
    int wid = threadIdx.x >> 5;
    #pragma unroll
    for (int o = 16; o > 0; o >>= 1) v += __shfl_down_sync(0xffffffffu, v, o);
    if (lane == 0) sred[wid] = v;
    __syncthreads();
    if (threadIdx.x < 32) {
        int nw = (blockDim.x + 31) >> 5;
        float x = (threadIdx.x < nw) ? sred[threadIdx.x] : 0.0f;
        #pragma unroll
        for (int o = 16; o > 0; o >>= 1) x += __shfl_down_sync(0xffffffffu, x, o);
        if (threadIdx.x == 0) sred[0] = x;
    }
    __syncthreads();
    float r = sred[0];
    __syncthreads();
    return r;
}

// ---------------- norms: |x| over D for (b, m) with stride-len layout ----------------
__global__ void norms_kernel(const float* __restrict__ E, float* __restrict__ out) {
    int idx = blockIdx.x * blockDim.x + threadIdx.x;   // over BATCH*len
    int b = idx >> 10;
    int m = idx & 1023;
    const float* p = E + (size_t)b * DIMD * MSZ + m;
    float s = 0.0f;
    #pragma unroll 8
    for (int d = 0; d < DIMD; d++) {
        float x = p[(size_t)d * MSZ];
        s += x * x;
    }
    out[idx] = sqrtf(s);
}

// ---------------- GEMM: K[b,m,n] = exp(-(1 - dot/denom)/l) ----------------
// A = src_emb (B,D,M), Bm = tgt_emb (B,D,N): dot = sum_d A[b,d,m]*Bm[b,d,n]
#define TM 128
#define TN 128
#define TK 8
__global__ void __launch_bounds__(256, 2) gemm_K_kernel(
        const float* __restrict__ A, const float* __restrict__ Bm,
        const float* __restrict__ lptr) {
    __shared__ float As[TK][TM];
    __shared__ float Bs[TK][TN];

    int b = blockIdx.z;
    int m0 = blockIdx.y * TM;
    int n0 = blockIdx.x * TN;
    int tid = threadIdx.x;
    int tx = tid & 15;        // n-direction
    int ty = tid >> 4;        // m-direction

    const float* Ab = A + (size_t)b * DIMD * MSZ + m0;
    const float* Bb = Bm + (size_t)b * DIMD * NSZ + n0;

    float acc[8][8];
    #pragma unroll
    for (int i = 0; i < 8; i++)
        #pragma unroll
        for (int j = 0; j < 8; j++) acc[i][j] = 0.0f;

    int lrow = tid >> 7;      // 0..1
    int lcol = tid & 127;

    for (int k = 0; k < DIMD; k += TK) {
        #pragma unroll
        for (int t = 0; t < TK; t += 2) {
            As[t + lrow][lcol] = Ab[(size_t)(k + t + lrow) * MSZ + lcol];
            Bs[t + lrow][lcol] = Bb[(size_t)(k + t + lrow) * NSZ + lcol];
        }
        __syncthreads();
        #pragma unroll
        for (int t = 0; t < TK; t++) {
            float4 a0 = *(const float4*)&As[t][ty * 8];
            float4 a1 = *(const float4*)&As[t][ty * 8 + 4];
            float4 b0 = *(const float4*)&Bs[t][tx * 8];
            float4 b1 = *(const float4*)&Bs[t][tx * 8 + 4];
            float av[8] = {a0.x, a0.y, a0.z, a0.w, a1.x, a1.y, a1.z, a1.w};
            float bv[8] = {b0.x, b0.y, b0.z, b0.w, b1.x, b1.y, b1.z, b1.w};
            #pragma unroll
            for (int i = 0; i < 8; i++)
                #pragma unroll
                for (int j = 0; j < 8; j++)
                    acc[i][j] += av[i] * bv[j];
        }
        __syncthreads();
    }

    float lval = lptr[0];
    float linv = 1.0f / fmaxf(lval, 1e-8f);
    float n1r[8], n2r[8];
    #pragma unroll
    for (int i = 0; i < 8; i++) n1r[i] = g_n1[b * MSZ + m0 + ty * 8 + i];
    #pragma unroll
    for (int j = 0; j < 8; j++) n2r[j] = g_n2[b * NSZ + n0 + tx * 8 + j];

    float* Kb = g_K + (size_t)b * MSZ * NSZ;
    #pragma unroll
    for (int i = 0; i < 8; i++) {
        int m = m0 + ty * 8 + i;
        float out[8];
        #pragma unroll
        for (int j = 0; j < 8; j++) {
            float denom = fmaxf(n1r[i] * n2r[j], 1e-6f);
            float C = 1.0f - acc[i][j] / denom;
            out[j] = expf(-C * linv);
        }
        size_t off = (size_t)m * NSZ + n0 + tx * 8;
        *(float4*)&Kb[off]     = make_float4(out[0], out[1], out[2], out[3]);
        *(float4*)&Kb[off + 4] = make_float4(out[4], out[5], out[6], out[7]);
    }
}

// ---------------- init u,v ----------------
__global__ void init_uv_kernel() {
    int idx = blockIdx.x * blockDim.x + threadIdx.x;
    if (idx < BATCH * MSZ) g_u[idx] = 1.0f / (float)MSZ;
    if (idx < BATCH * NSZ) g_v[idx] = 1.0f / (float)NSZ;
}

// ---------------- Sinkhorn u-update: u = (a / clip(K v, 1e-8))^fi ----------------
__global__ void sink_u_kernel(const float* __restrict__ lptr, const float* __restrict__ rptr) {
    __shared__ float sred[32];
    int bm = blockIdx.x;              // b*MSZ + m
    int b = bm >> 10;
    const float4* Krow = (const float4*)(g_K + (size_t)bm * NSZ);
    const float4* vrow = (const float4*)(g_v + b * NSZ);
    int t = threadIdx.x;              // 256 threads, N/4 = 256 float4s
    float4 kk = Krow[t];
    float4 vv = vrow[t];
    float s = kk.x * vv.x + kk.y * vv.y + kk.z * vv.z + kk.w * vv.w;
    s = blockReduceB(s, sred);
    if (threadIdx.x == 0) {
        float lv = lptr[0], rv = rptr[0];
        float fi = rv / fmaxf(rv + lv, 1e-8f);
        float a = 1.0f / (float)MSZ;
        g_u[bm] = powf(a / fmaxf(s, 1e-8f), fi);
    }
}

// ---------------- Sinkhorn v-update: partial column sums (deterministic split) ----------------
__global__ void sink_vpart_kernel() {
    int b = blockIdx.y;
    int n = blockIdx.x * blockDim.x + threadIdx.x;
    int mz = blockIdx.z;
    const float* Kb = g_K + (size_t)b * MSZ * NSZ + n;
    const float* ub = g_u + b * MSZ;
    int m0 = mz * (MSZ / MSPLIT);
    float s = 0.0f;
    #pragma unroll 8
    for (int m = m0; m < m0 + MSZ / MSPLIT; m++)
        s += Kb[(size_t)m * NSZ] * ub[m];
    g_vpart[(mz * BATCH + b) * NSZ + n] = s;
}

__global__ void sink_vpow_kernel(const float* __restrict__ lptr, const float* __restrict__ rptr) {
    int idx = blockIdx.x * blockDim.x + threadIdx.x;   // over BATCH*NSZ
    int b = idx >> 10;
    int n = idx & 1023;
    float s = 0.0f;
    #pragma unroll
    for (int z = 0; z < MSPLIT; z++)
        s += g_vpart[(z * BATCH + b) * NSZ + n];
    float lv = lptr[0], rv = rptr[0];
    float fi = rv / fmaxf(rv + lv, 1e-8f);
    float bb = 1.0f / (float)NSZ;
    g_v[idx] = powf(bb / fmaxf(s, 1e-8f), fi);
}

// ---------------- P = u*K*v, row sums, weighted_ref (fused, one pass over K) ----------------
__global__ void compute_P_kernel(const float* __restrict__ tgt, float* __restrict__ Pout) {
    __shared__ float sred[32];
    int bm = blockIdx.x;
    int b = bm >> 10;
    float uu = g_u[bm];
    const float4* Krow = (const float4*)(g_K + (size_t)bm * NSZ);
    const float4* vrow = (const float4*)(g_v + b * NSZ);
    float4* Prow = (float4*)(Pout + (size_t)bm * NSZ);
    const float4* t0 = (const float4*)(tgt + ((size_t)b * 3 + 0) * NSZ);
    const float4* t1 = (const float4*)(tgt + ((size_t)b * 3 + 1) * NSZ);
    const float4* t2 = (const float4*)(tgt + ((size_t)b * 3 + 2) * NSZ);

    int t = threadIdx.x;
    float4 kk = Krow[t];
    float4 vv = vrow[t];
    float4 p;
    p.x = uu * kk.x * vv.x;
    p.y = uu * kk.y * vv.y;
    p.z = uu * kk.z * vv.z;
    p.w = uu * kk.w * vv.w;
    Prow[t] = p;

    float4 a0 = t0[t], a1 = t1[t], a2 = t2[t];
    float rs = p.x + p.y + p.z + p.w;
    float w0 = p.x * a0.x + p.y * a0.y + p.z * a0.z + p.w * a0.w;
    float w1 = p.x * a1.x + p.y * a1.y + p.z * a1.z + p.w * a1.w;
    float w2 = p.x * a2.x + p.y * a2.y + p.z * a2.z + p.w * a2.w;

    rs = blockReduceB(rs, sred);
    w0 = blockReduceB(w0, sred);
    w1 = blockReduceB(w1, sred);
    w2 = blockReduceB(w2, sred);
    if (threadIdx.x == 0) {
        g_rowS[bm] = rs;
        float inv = 1.0f / (rs + 1e-6f);
        g_wref[bm * 3 + 0] = w0 * inv;
        g_wref[bm * 3 + 1] = w1 * inv;
        g_wref[bm * 3 + 2] = w2 * inv;
    }
}

// ---------------- per-batch centroids + covariance ----------------
__global__ void cov_kernel(const float* __restrict__ src) {
    __shared__ float sred[32];
    int b = blockIdx.x;
    int t = threadIdx.x;   // 256

    // total row mass
    float s = 0.0f;
    for (int m = t; m < MSZ; m += 256) s += g_rowS[b * MSZ + m];
    float S = blockReduceB(s, sred);
    float inv = 1.0f / (S + 1e-6f);

    // centroids
    float ca[3] = {0, 0, 0}, cb[3] = {0, 0, 0};
    for (int m = t; m < MSZ; m += 256) {
        float w = g_rowS[b * MSZ + m] * inv;
        #pragma unroll
        for (int d = 0; d < 3; d++) {
            ca[d] += w * src[((size_t)b * 3 + d) * MSZ + m];
            cb[d] += w * g_wref[(b * MSZ + m) * 3 + d];
        }
    }
    float CA[3], CB[3];
    #pragma unroll
    for (int d = 0; d < 3; d++) CA[d] = blockReduceB(ca[d], sred);
    #pragma unroll
    for (int d = 0; d < 3; d++) CB[d] = blockReduceB(cb[d], sred);

    // covariance
    float cv[9] = {0, 0, 0, 0, 0, 0, 0, 0, 0};
    for (int m = t; m < MSZ; m += 256) {
        float w = g_rowS[b * MSZ + m] * inv;
        float ac[3], bc[3];
        #pragma unroll
        for (int d = 0; d < 3; d++) {
            ac[d] = src[((size_t)b * 3 + d) * MSZ + m] - CA[d];
            bc[d] = g_wref[(b * MSZ + m) * 3 + d] - CB[d];
        }
        #pragma unroll
        for (int i = 0; i < 3; i++)
            #pragma unroll
            for (int j = 0; j < 3; j++)
                cv[i * 3 + j] += ac[i] * bc[j] * w;
    }
    #pragma unroll
    for (int k = 0; k < 9; k++) {
        float r = blockReduceB(cv[k], sred);
        if (t == 0) g_cov[b * 9 + k] = r;
    }
    if (t == 0) {
        #pragma unroll
        for (int d = 0; d < 3; d++) { g_ca[b * 3 + d] = CA[d]; g_cb[b * 3 + d] = CB[d]; }
    }
}

// ---------------- 3x3 SVD (fp64 Jacobi) + Kabsch R,t ----------------
__global__ void svd_kernel(float* __restrict__ out) {
    int b = threadIdx.x;
    if (b >= BATCH) return;

    double A[3][3];
    #pragma unroll
    for (int i = 0; i < 3; i++)
        #pragma unroll
        for (int j = 0; j < 3; j++)
            A[i][j] = (double)g_cov[b * 9 + i * 3 + j];

    // S = A^T A
    double S[3][3];
    #pragma unroll
    for (int i = 0; i < 3; i++)
        #pragma unroll
        for (int j = 0; j < 3; j++) {
            double acc = 0.0;
            #pragma unroll
            for (int k = 0; k < 3; k++) acc += A[k][i] * A[k][j];
            S[i][j] = acc;
        }

    double V[3][3] = {{1, 0, 0}, {0, 1, 0}, {0, 0, 1}};
    const int PP[3] = {0, 0, 1};
    const int QQ[3] = {1, 2, 2};
    for (int sweep = 0; sweep < 20; sweep++) {
        for (int r = 0; r < 3; r++) {
            int p = PP[r], q = QQ[r];
            double apq = S[p][q];
            if (apq == 0.0) continue;
            double theta = (S[q][q] - S[p][p]) / (2.0 * apq);
            double tt = copysign(1.0, theta) / (fabs(theta) + sqrt(1.0 + theta * theta));
            double c = 1.0 / sqrt(1.0 + tt * tt);
            double sn = tt * c;
            // S <- J^T S J   (J_pp=c, J_qq=c, J_pq=sn, J_qp=-sn)
            for (int k = 0; k < 3; k++) {
                double skp = S[k][p], skq = S[k][q];
                S[k][p] = c * skp - sn * skq;
                S[k][q] = sn * skp + c * skq;
            }
            for (int k = 0; k < 3; k++) {
                double spk = S[p][k], sqk = S[q][k];
                S[p][k] = c * spk - sn * sqk;
                S[q][k] = sn * spk + c * sqk;
            }
            for (int k = 0; k < 3; k++) {
                double vkp = V[k][p], vkq = V[k][q];
                V[k][p] = c * vkp - sn * vkq;
                V[k][q] = sn * vkp + c * vkq;
            }
        }
    }

    // sort eigenvalues descending
    double ev[3] = {S[0][0], S[1][1], S[2][2]};
    int idx[3] = {0, 1, 2};
    for (int i = 0; i < 2; i++)
        for (int j = i + 1; j < 3; j++)
            if (ev[idx[j]] > ev[idx[i]]) { int tmp = idx[i]; idx[i] = idx[j]; idx[j] = tmp; }

    double Vs[3][3];
    #pragma unroll
    for (int k = 0; k < 3; k++)
        for (int i = 0; i < 3; i++)
            Vs[k][i] = V[k][idx[i]];

    // U = A Vs / sigma (normalize columns)
    double U[3][3];
    double nrm[3];
    for (int i = 0; i < 3; i++) {
        double u0 = A[0][0] * Vs[0][i] + A[0][1] * Vs[1][i] + A[0][2] * Vs[2][i];
        double u1 = A[1][0] * Vs[0][i] + A[1][1] * Vs[1][i] + A[1][2] * Vs[2][i];
        double u2 = A[2][0] * Vs[0][i] + A[2][1] * Vs[1][i] + A[2][2] * Vs[2][i];
        double nm = sqrt(u0 * u0 + u1 * u1 + u2 * u2);
        nrm[i] = nm;
        double in = (nm > 1e-300) ? 1.0 / nm : 0.0;
        U[0][i] = u0 * in; U[1][i] = u1 * in; U[2][i] = u2 * in;
    }
    // degenerate smallest singular value -> complete with cross product
    if (nrm[2] < 1e-12 * fmax(nrm[0], 1e-300)) {
        U[0][2] = U[1][0] * U[2][1] - U[2][0] * U[1][1];
        U[1][2] = U[2][0] * U[0][1] - U[0][0] * U[2][1];
        U[2][2] = U[0][0] * U[1][1] - U[1][0] * U[0][1];
    }

    // rot_pos = Vs U^T
    double R[3][3];
    for (int i = 0; i < 3; i++)
        for (int j = 0; j < 3; j++)
            R[i][j] = Vs[i][0] * U[j][0] + Vs[i][1] * U[j][1] + Vs[i][2] * U[j][2];

    double det = R[0][0] * (R[1][1] * R[2][2] - R[1][2] * R[2][1])
               - R[0][1] * (R[1][0] * R[2][2] - R[1][2] * R[2][0])
               + R[0][2] * (R[1][0] * R[2][1] - R[1][1] * R[2][0]);
    if (!(det > 0.0)) {
        // flip third column of Vs: rot_neg = rot_pos - 2 * Vs[:,2] U[:,2]^T
        for (int i = 0; i < 3; i++)
            for (int j = 0; j < 3; j++)
                R[i][j] -= 2.0 * Vs[i][2] * U[j][2];
    }

    double ca[3] = {(double)g_ca[b * 3], (double)g_ca[b * 3 + 1], (double)g_ca[b * 3 + 2]};
    double cb[3] = {(double)g_cb[b * 3], (double)g_cb[b * 3 + 1], (double)g_cb[b * 3 + 2]};
    double tv[3];
    for (int i = 0; i < 3; i++)
        tv[i] = -(R[i][0] * ca[0] + R[i][1] * ca[1] + R[i][2] * ca[2]) + cb[i];

    // outputs: R [0 : 288), t [288 : 384)
    for (int i = 0; i < 3; i++)
        for (int j = 0; j < 3; j++)
            out[b * 9 + i * 3 + j] = (float)R[i][j];
    for (int i = 0; i < 3; i++)
        out[288 + b * 3 + i] = (float)tv[i];
}

// ---------------- launch ----------------
extern "C" void kernel_launch(void* const* d_in, const int* in_sizes, int n_in,
                              void* d_out, int out_size) {
    const float* src_emb = (const float*)d_in[0];
    const float* tgt_emb = (const float*)d_in[1];
    const float* src     = (const float*)d_in[2];
    const float* tgt     = (const float*)d_in[3];
    const float* lptr    = (const float*)d_in[4];
    const float* rptr    = (const float*)d_in[5];
    float* out = (float*)d_out;
    float* Pout = out + BATCH * 9 + BATCH * 3;   // P region

    float* dn1; cudaGetSymbolAddress((void**)&dn1, g_n1);
    float* dn2; cudaGetSymbolAddress((void**)&dn2, g_n2);

    norms_kernel<<<(BATCH * MSZ) / 256, 256>>>(src_emb, dn1);
    norms_kernel<<<(BATCH * NSZ) / 256, 256>>>(tgt_emb, dn2);

    dim3 ggrid(NSZ / TN, MSZ / TM, BATCH);
    gemm_K_kernel<<<ggrid, 256>>>(src_emb, tgt_emb, lptr);

    init_uv_kernel<<<(BATCH * MSZ) / 256, 256>>>();

    for (int it = 0; it < SINK_ITERS; it++) {
        sink_u_kernel<<<BATCH * MSZ, 256>>>(lptr, rptr);
        dim3 vgrid(NSZ / 256, BATCH, MSPLIT);
        sink_vpart_kernel<<<vgrid, 256>>>();
        sink_vpow_kernel<<<(BATCH * NSZ) / 256, 256>>>(lptr, rptr);
    }

    compute_P_kernel<<<BATCH * MSZ, 256>>>(tgt, Pout);
    cov_kernel<<<BATCH, 256>>>(src);
    svd_kernel<<<1, 32>>>(out);
}

// round 4
// speedup vs baseline: 1.9994x; 1.9994x over previous
#include <cuda_runtime.h>
#include <math.h>
#include <stdint.h>

#define BATCH 32
#define DIMD  512
#define MSZ   1024
#define NSZ   1024
#define SINK_ITERS 5
#define MSPLIT 32

// ---------------- device scratch (static: no allocations) ----------------
__device__ float g_K[(size_t)BATCH * MSZ * NSZ];       // 134 MB kernel matrix
__device__ float g_n1[BATCH * MSZ];
__device__ float g_n2[BATCH * NSZ];
__device__ float g_u[BATCH * MSZ];
__device__ float g_v[BATCH * NSZ];
__device__ float g_vpart[(size_t)MSPLIT * BATCH * NSZ];
__device__ float g_rowS[BATCH * MSZ];
__device__ float g_wref[BATCH * MSZ * 3];
__device__ float g_cov[BATCH * 9];
__device__ float g_ca[BATCH * 3];
__device__ float g_cb[BATCH * 3];

// ---------------- PTX helpers (baseline features only, no sm_103a-specific) ----
#define CP_ASYNC16(dst, src) \
    asm volatile("cp.async.cg.shared.global [%0], [%1], 16;" :: "r"(dst), "l"(src))
#define CP_COMMIT() asm volatile("cp.async.commit_group;" ::: "memory")
#define CP_WAIT(n)  asm volatile("cp.async.wait_group %0;" :: "n"(n) : "memory")

__device__ __forceinline__ uint32_t smem_u32(const void* p) {
    uint32_t a;
    asm("{ .reg .u64 t; cvta.to.shared.u64 t, %1; cvt.u32.u64 %0, t; }" : "=r"(a) : "l"(p));
    return a;
}
__device__ __forceinline__ uint32_t f2tf(float x) {
    uint32_t r;
    asm("cvt.rna.tf32.f32 %0, %1;" : "=r"(r) : "f"(x));
    return r;
}
__device__ __forceinline__ void mma_tf32(float* c, uint32_t a0, uint32_t a1,
                                         uint32_t a2, uint32_t a3,
                                         uint32_t b0, uint32_t b1) {
    asm volatile(
        "mma.sync.aligned.m16n8k8.row.col.f32.tf32.tf32.f32 "
        "{%0,%1,%2,%3},{%4,%5,%6,%7},{%8,%9},{%0,%1,%2,%3};"
        : "+f"(c[0]), "+f"(c[1]), "+f"(c[2]), "+f"(c[3])
        : "r"(a0), "r"(a1), "r"(a2), "r"(a3), "r"(b0), "r"(b1));
}

// ---------------- generic helpers ----------------
__device__ __forceinline__ float blockReduceB(float v, volatile float* sred) {
    int lane = threadIdx.x & 31;
    int wid = threadIdx.x >> 5;
    #pragma unroll
    for (int o = 16; o > 0; o >>= 1) v += __shfl_down_sync(0xffffffffu, v, o);
    if (lane == 0) sred[wid] = v;
    __syncthreads();
    if (threadIdx.x < 32) {
        int nw = (blockDim.x + 31) >> 5;
        float x = (threadIdx.x < nw) ? sred[threadIdx.x] : 0.0f;
        #pragma unroll
        for (int o = 16; o > 0; o >>= 1) x += __shfl_down_sync(0xffffffffu, x, o);
        if (threadIdx.x == 0) sred[0] = x;
    }
    __syncthreads();
    float r = sred[0];
    __syncthreads();
    return r;
}

// ---------------- norms over D for (b, m), layout (B, D, len) ----------------
__global__ void norms_kernel(const float* __restrict__ E, float* __restrict__ out) {
    int idx = blockIdx.x * blockDim.x + threadIdx.x;
    int b = idx >> 10;
    int m = idx & 1023;
    const float* p = E + (size_t)b * DIMD * MSZ + m;
    float s = 0.0f;
    #pragma unroll 8
    for (int d = 0; d < DIMD; d++) {
        float x = p[(size_t)d * MSZ];
        s += x * x;
    }
    out[idx] = sqrtf(s);
}

// ---------------- TF32 mma.sync GEMM + exp epilogue ----------------
// K[b,m,n] = exp(-(1 - dot/denom)/l)
// A tiles loaded directly from (B, D, M) layout (D rows are M-contiguous).
#define KC 16
#define SSTR 136   // smem row stride (floats): 16B aligned, conflict-free frags
__global__ void __launch_bounds__(256) gemm_mma_kernel(
        const float* __restrict__ Ae, const float* __restrict__ Be,
        const float* __restrict__ lptr) {
    __shared__ float sA[2][KC][SSTR];
    __shared__ float sB[2][KC][SSTR];

    int b = blockIdx.z;
    int m0 = blockIdx.y * 128;
    int n0 = blockIdx.x * 128;
    int tid = threadIdx.x;
    int wid = tid >> 5;
    int lane = tid & 31;
    int g = lane >> 2;          // group 0..7
    int tig = lane & 3;         // thread-in-group 0..3
    int warp_m = (wid >> 2) * 64;   // 2 warps in m
    int warp_n = (wid & 3) * 32;    // 4 warps in n

    const float* Ab = Ae + (size_t)b * DIMD * MSZ;
    const float* Bb = Be + (size_t)b * DIMD * NSZ;
    uint32_t sA_u = smem_u32(&sA[0][0][0]);
    uint32_t sB_u = smem_u32(&sB[0][0][0]);

    float acc[4][4][4];
    #pragma unroll
    for (int mi = 0; mi < 4; mi++)
        #pragma unroll
        for (int ni = 0; ni < 4; ni++)
            #pragma unroll
            for (int q = 0; q < 4; q++) acc[mi][ni][q] = 0.0f;

    // prologue: load chunk 0 into buf 0
    {
        #pragma unroll
        for (int i = 0; i < 2; i++) {
            int slot = tid + i * 256;          // 0..511
            int kr = slot >> 5;                // 16 rows
            int c4 = slot & 31;                // 32 float4 per row
            const float* ga = Ab + (size_t)kr * MSZ + m0 + c4 * 4;
            const float* gb = Bb + (size_t)kr * NSZ + n0 + c4 * 4;
            uint32_t off = (uint32_t)(kr * SSTR + c4 * 4) * 4u;
            CP_ASYNC16(sA_u + off, ga);
            CP_ASYNC16(sB_u + off, gb);
        }
        CP_COMMIT();
    }

    const int NCH = DIMD / KC;   // 32
    for (int c = 0; c < NCH; c++) {
        if (c + 1 < NCH) {
            int buf = (c + 1) & 1;
            #pragma unroll
            for (int i = 0; i < 2; i++) {
                int slot = tid + i * 256;
                int kr = slot >> 5;
                int c4 = slot & 31;
                const float* ga = Ab + (size_t)((c + 1) * KC + kr) * MSZ + m0 + c4 * 4;
                const float* gb = Bb + (size_t)((c + 1) * KC + kr) * NSZ + n0 + c4 * 4;
                uint32_t off = (uint32_t)((buf * KC + kr) * SSTR + c4 * 4) * 4u;
                CP_ASYNC16(sA_u + off, ga);
                CP_ASYNC16(sB_u + off, gb);
            }
        }
        CP_COMMIT();
        CP_WAIT(1);
        __syncthreads();

        int cb = c & 1;
        #pragma unroll
        for (int ks = 0; ks < 2; ks++) {
            int k0 = ks * 8;
            // B fragments
            uint32_t bf[4][2];
            #pragma unroll
            for (int ni = 0; ni < 4; ni++) {
                int nn = warp_n + ni * 8 + g;
                bf[ni][0] = f2tf(sB[cb][k0 + tig][nn]);
                bf[ni][1] = f2tf(sB[cb][k0 + tig + 4][nn]);
            }
            #pragma unroll
            for (int mi = 0; mi < 4; mi++) {
                int mm = warp_m + mi * 16 + g;
                uint32_t a0 = f2tf(sA[cb][k0 + tig][mm]);
                uint32_t a1 = f2tf(sA[cb][k0 + tig][mm + 8]);
                uint32_t a2 = f2tf(sA[cb][k0 + tig + 4][mm]);
                uint32_t a3 = f2tf(sA[cb][k0 + tig + 4][mm + 8]);
                #pragma unroll
                for (int ni = 0; ni < 4; ni++)
                    mma_tf32(acc[mi][ni], a0, a1, a2, a3, bf[ni][0], bf[ni][1]);
            }
        }
        __syncthreads();
    }

    // epilogue: cosine + exp, write K
    float linv = 1.0f / fmaxf(lptr[0], 1e-8f);
    float n2r[8];
    #pragma unroll
    for (int ni = 0; ni < 4; ni++) {
        int nc = n0 + warp_n + ni * 8 + 2 * tig;
        n2r[ni * 2]     = g_n2[b * NSZ + nc];
        n2r[ni * 2 + 1] = g_n2[b * NSZ + nc + 1];
    }
    #pragma unroll
    for (int mi = 0; mi < 4; mi++) {
        #pragma unroll
        for (int half = 0; half < 2; half++) {
            int m = m0 + warp_m + mi * 16 + g + half * 8;
            float n1v = g_n1[b * MSZ + m];
            float* Krow = g_K + ((size_t)(b * MSZ + m)) * NSZ + n0 + warp_n;
            #pragma unroll
            for (int ni = 0; ni < 4; ni++) {
                float x0 = acc[mi][ni][half * 2 + 0];
                float x1 = acc[mi][ni][half * 2 + 1];
                float d0 = fmaxf(n1v * n2r[ni * 2], 1e-6f);
                float d1 = fmaxf(n1v * n2r[ni * 2 + 1], 1e-6f);
                float o0 = expf(-(1.0f - x0 / d0) * linv);
                float o1 = expf(-(1.0f - x1 / d1) * linv);
                *(float2*)&Krow[ni * 8 + 2 * tig] = make_float2(o0, o1);
            }
        }
    }
}

// ---------------- init u,v ----------------
__global__ void init_uv_kernel() {
    int idx = blockIdx.x * blockDim.x + threadIdx.x;
    if (idx < BATCH * MSZ) g_u[idx] = 1.0f / (float)MSZ;
    if (idx < BATCH * NSZ) g_v[idx] = 1.0f / (float)NSZ;
}

// ---------------- fused Sinkhorn iteration: u update + column partials ----------------
__global__ void __launch_bounds__(256) sink_fused_kernel(
        const float* __restrict__ lptr, const float* __restrict__ rptr) {
    __shared__ float su[32];
    int b = blockIdx.y;
    int m0 = blockIdx.x * 32;
    int tid = threadIdx.x;
    int wid = tid >> 5;
    int lane = tid & 31;

    float lv = lptr[0], rv = rptr[0];
    float fi = rv / fmaxf(rv + lv, 1e-8f);
    float a = 1.0f / (float)MSZ;

    const float4* v4 = (const float4*)(g_v + b * NSZ);

    // Phase A: u for rows m0..m0+31 (warp w handles rows w*4..w*4+3)
    #pragma unroll
    for (int rr = 0; rr < 4; rr++) {
        int r = (wid << 2) | rr;
        const float4* Kr = (const float4*)(g_K + ((size_t)(b * MSZ + m0 + r)) * NSZ);
        float s = 0.0f;
        #pragma unroll
        for (int j = 0; j < 8; j++) {
            float4 kk = Kr[j * 32 + lane];
            float4 vv = v4[j * 32 + lane];
            s += kk.x * vv.x + kk.y * vv.y + kk.z * vv.z + kk.w * vv.w;
        }
        #pragma unroll
        for (int o = 16; o > 0; o >>= 1) s += __shfl_down_sync(0xffffffffu, s, o);
        if (lane == 0) {
            float uu = powf(a / fmaxf(s, 1e-8f), fi);
            g_u[b * MSZ + m0 + r] = uu;
            su[r] = uu;
        }
    }
    __syncthreads();

    // Phase B: column partials over these 32 rows (thread owns 4 cols)
    const float* Kb = g_K + (size_t)(b * MSZ + m0) * NSZ;
    float4 acc = make_float4(0.f, 0.f, 0.f, 0.f);
    #pragma unroll 4
    for (int r = 0; r < 32; r++) {
        float uu = su[r];
        float4 kk = *(const float4*)&Kb[(size_t)r * NSZ + tid * 4];
        acc.x += uu * kk.x;
        acc.y += uu * kk.y;
        acc.z += uu * kk.z;
        acc.w += uu * kk.w;
    }
    *(float4*)&g_vpart[((size_t)blockIdx.x * BATCH + b) * NSZ + tid * 4] = acc;
}

// ---------------- v = (b / clip(colsum, eps))^fi ----------------
__global__ void sink_vpow_kernel(const float* __restrict__ lptr, const float* __restrict__ rptr) {
    int idx = blockIdx.x * blockDim.x + threadIdx.x;
    int b = idx >> 10;
    int n = idx & 1023;
    float s = 0.0f;
    #pragma unroll
    for (int z = 0; z < MSPLIT; z++)
        s += g_vpart[((size_t)z * BATCH + b) * NSZ + n];
    float lv = lptr[0], rv = rptr[0];
    float fi = rv / fmaxf(rv + lv, 1e-8f);
    float bb = 1.0f / (float)NSZ;
    g_v[idx] = powf(bb / fmaxf(s, 1e-8f), fi);
}

// ---------------- P = u*K*v, row sums, weighted_ref (one pass over K) ----------------
__global__ void compute_P_kernel(const float* __restrict__ tgt, float* __restrict__ Pout) {
    __shared__ float sred[32];
    int bm = blockIdx.x;
    int b = bm >> 10;
    float uu = g_u[bm];
    const float4* Krow = (const float4*)(g_K + (size_t)bm * NSZ);
    const float4* vrow = (const float4*)(g_v + b * NSZ);
    float4* Prow = (float4*)(Pout + (size_t)bm * NSZ);
    const float4* t0 = (const float4*)(tgt + ((size_t)b * 3 + 0) * NSZ);
    const float4* t1 = (const float4*)(tgt + ((size_t)b * 3 + 1) * NSZ);
    const float4* t2 = (const float4*)(tgt + ((size_t)b * 3 + 2) * NSZ);

    int t = threadIdx.x;
    float4 kk = Krow[t];
    float4 vv = vrow[t];
    float4 p;
    p.x = uu * kk.x * vv.x;
    p.y = uu * kk.y * vv.y;
    p.z = uu * kk.z * vv.z;
    p.w = uu * kk.w * vv.w;
    Prow[t] = p;

    float4 a0 = t0[t], a1 = t1[t], a2 = t2[t];
    float rs = p.x + p.y + p.z + p.w;
    float w0 = p.x * a0.x + p.y * a0.y + p.z * a0.z + p.w * a0.w;
    float w1 = p.x * a1.x + p.y * a1.y + p.z * a1.z + p.w * a1.w;
    float w2 = p.x * a2.x + p.y * a2.y + p.z * a2.z + p.w * a2.w;

    rs = blockReduceB(rs, sred);
    w0 = blockReduceB(w0, sred);
    w1 = blockReduceB(w1, sred);
    w2 = blockReduceB(w2, sred);
    if (threadIdx.x == 0) {
        g_rowS[bm] = rs;
        float inv = 1.0f / (rs + 1e-6f);
        g_wref[bm * 3 + 0] = w0 * inv;
        g_wref[bm * 3 + 1] = w1 * inv;
        g_wref[bm * 3 + 2] = w2 * inv;
    }
}

// ---------------- per-batch centroids + covariance ----------------
__global__ void cov_kernel(const float* __restrict__ src) {
    __shared__ float sred[32];
    int b = blockIdx.x;
    int t = threadIdx.x;

    float s = 0.0f;
    for (int m = t; m < MSZ; m += 256) s += g_rowS[b * MSZ + m];
    float S = blockReduceB(s, sred);
    float inv = 1.0f / (S + 1e-6f);

    float ca[3] = {0, 0, 0}, cb[3] = {0, 0, 0};
    for (int m = t; m < MSZ; m += 256) {
        float w = g_rowS[b * MSZ + m] * inv;
        #pragma unroll
        for (int d = 0; d < 3; d++) {
            ca[d] += w * src[((size_t)b * 3 + d) * MSZ + m];
            cb[d] += w * g_wref[(b * MSZ + m) * 3 + d];
        }
    }
    float CA[3], CB[3];
    #pragma unroll
    for (int d = 0; d < 3; d++) CA[d] = blockReduceB(ca[d], sred);
    #pragma unroll
    for (int d = 0; d < 3; d++) CB[d] = blockReduceB(cb[d], sred);

    float cv[9] = {0, 0, 0, 0, 0, 0, 0, 0, 0};
    for (int m = t; m < MSZ; m += 256) {
        float w = g_rowS[b * MSZ + m] * inv;
        float ac[3], bc[3];
        #pragma unroll
        for (int d = 0; d < 3; d++) {
            ac[d] = src[((size_t)b * 3 + d) * MSZ + m] - CA[d];
            bc[d] = g_wref[(b * MSZ + m) * 3 + d] - CB[d];
        }
        #pragma unroll
        for (int i = 0; i < 3; i++)
            #pragma unroll
            for (int j = 0; j < 3; j++)
                cv[i * 3 + j] += ac[i] * bc[j] * w;
    }
    #pragma unroll
    for (int k = 0; k < 9; k++) {
        float r = blockReduceB(cv[k], sred);
        if (t == 0) g_cov[b * 9 + k] = r;
    }
    if (t == 0) {
        #pragma unroll
        for (int d = 0; d < 3; d++) { g_ca[b * 3 + d] = CA[d]; g_cb[b * 3 + d] = CB[d]; }
    }
}

// ---------------- 3x3 SVD (fp64 Jacobi) + Kabsch R,t ----------------
__global__ void svd_kernel(float* __restrict__ out) {
    int b = threadIdx.x;
    if (b >= BATCH) return;

    double A[3][3];
    #pragma unroll
    for (int i = 0; i < 3; i++)
        #pragma unroll
        for (int j = 0; j < 3; j++)
            A[i][j] = (double)g_cov[b * 9 + i * 3 + j];

    double S[3][3];
    #pragma unroll
    for (int i = 0; i < 3; i++)
        #pragma unroll
        for (int j = 0; j < 3; j++) {
            double acc = 0.0;
            #pragma unroll
            for (int k = 0; k < 3; k++) acc += A[k][i] * A[k][j];
            S[i][j] = acc;
        }

    double V[3][3] = {{1, 0, 0}, {0, 1, 0}, {0, 0, 1}};
    const int PP[3] = {0, 0, 1};
    const int QQ[3] = {1, 2, 2};
    for (int sweep = 0; sweep < 20; sweep++) {
        for (int r = 0; r < 3; r++) {
            int p = PP[r], q = QQ[r];
            double apq = S[p][q];
            if (apq == 0.0) continue;
            double theta = (S[q][q] - S[p][p]) / (2.0 * apq);
            double tt = copysign(1.0, theta) / (fabs(theta) + sqrt(1.0 + theta * theta));
            double c = 1.0 / sqrt(1.0 + tt * tt);
            double sn = tt * c;
            for (int k = 0; k < 3; k++) {
                double skp = S[k][p], skq = S[k][q];
                S[k][p] = c * skp - sn * skq;
                S[k][q] = sn * skp + c * skq;
            }
            for (int k = 0; k < 3; k++) {
                double spk = S[p][k], sqk = S[q][k];
                S[p][k] = c * spk - sn * sqk;
                S[q][k] = sn * spk + c * sqk;
            }
            for (int k = 0; k < 3; k++) {
                double vkp = V[k][p], vkq = V[k][q];
                V[k][p] = c * vkp - sn * vkq;
                V[k][q] = sn * vkp + c * vkq;
            }
        }
    }

    double ev[3] = {S[0][0], S[1][1], S[2][2]};
    int idx[3] = {0, 1, 2};
    for (int i = 0; i < 2; i++)
        for (int j = i + 1; j < 3; j++)
            if (ev[idx[j]] > ev[idx[i]]) { int tmp = idx[i]; idx[i] = idx[j]; idx[j] = tmp; }

    double Vs[3][3];
    #pragma unroll
    for (int k = 0; k < 3; k++)
        for (int i = 0; i < 3; i++)
            Vs[k][i] = V[k][idx[i]];

    double U[3][3];
    double nrm[3];
    for (int i = 0; i < 3; i++) {
        double u0 = A[0][0] * Vs[0][i] + A[0][1] * Vs[1][i] + A[0][2] * Vs[2][i];
        double u1 = A[1][0] * Vs[0][i] + A[1][1] * Vs[1][i] + A[1][2] * Vs[2][i];
        double u2 = A[2][0] * Vs[0][i] + A[2][1] * Vs[1][i] + A[2][2] * Vs[2][i];
        double nm = sqrt(u0 * u0 + u1 * u1 + u2 * u2);
        nrm[i] = nm;
        double in = (nm > 1e-300) ? 1.0 / nm : 0.0;
        U[0][i] = u0 * in; U[1][i] = u1 * in; U[2][i] = u2 * in;
    }
    if (nrm[2] < 1e-12 * fmax(nrm[0], 1e-300)) {
        U[0][2] = U[1][0] * U[2][1] - U[2][0] * U[1][1];
        U[1][2] = U[2][0] * U[0][1] - U[0][0] * U[2][1];
        U[2][2] = U[0][0] * U[1][1] - U[1][0] * U[0][1];
    }

    double R[3][3];
    for (int i = 0; i < 3; i++)
        for (int j = 0; j < 3; j++)
            R[i][j] = Vs[i][0] * U[j][0] + Vs[i][1] * U[j][1] + Vs[i][2] * U[j][2];

    double det = R[0][0] * (R[1][1] * R[2][2] - R[1][2] * R[2][1])
               - R[0][1] * (R[1][0] * R[2][2] - R[1][2] * R[2][0])
               + R[0][2] * (R[1][0] * R[2][1] - R[1][1] * R[2][0]);
    if (!(det > 0.0)) {
        for (int i = 0; i < 3; i++)
            for (int j = 0; j < 3; j++)
                R[i][j] -= 2.0 * Vs[i][2] * U[j][2];
    }

    double ca[3] = {(double)g_ca[b * 3], (double)g_ca[b * 3 + 1], (double)g_ca[b * 3 + 2]};
    double cb[3] = {(double)g_cb[b * 3], (double)g_cb[b * 3 + 1], (double)g_cb[b * 3 + 2]};
    double tv[3];
    for (int i = 0; i < 3; i++)
        tv[i] = -(R[i][0] * ca[0] + R[i][1] * ca[1] + R[i][2] * ca[2]) + cb[i];

    for (int i = 0; i < 3; i++)
        for (int j = 0; j < 3; j++)
            out[b * 9 + i * 3 + j] = (float)R[i][j];
    for (int i = 0; i < 3; i++)
        out[288 + b * 3 + i] = (float)tv[i];
}

// ---------------- launch ----------------
extern "C" void kernel_launch(void* const* d_in, const int* in_sizes, int n_in,
                              void* d_out, int out_size) {
    const float* src_emb = (const float*)d_in[0];
    const float* tgt_emb = (const float*)d_in[1];
    const float* src     = (const float*)d_in[2];
    const float* tgt     = (const float*)d_in[3];
    const float* lptr    = (const float*)d_in[4];
    const float* rptr    = (const float*)d_in[5];
    float* out = (float*)d_out;
    float* Pout = out + BATCH * 9 + BATCH * 3;

    float* dn1; cudaGetSymbolAddress((void**)&dn1, g_n1);
    float* dn2; cudaGetSymbolAddress((void**)&dn2, g_n2);

    norms_kernel<<<(BATCH * MSZ) / 256, 256>>>(src_emb, dn1);
    norms_kernel<<<(BATCH * NSZ) / 256, 256>>>(tgt_emb, dn2);

    dim3 ggrid(NSZ / 128, MSZ / 128, BATCH);
    gemm_mma_kernel<<<ggrid, 256>>>(src_emb, tgt_emb, lptr);

    init_uv_kernel<<<(BATCH * MSZ) / 256, 256>>>();

    for (int it = 0; it < SINK_ITERS; it++) {
        dim3 sgrid(MSZ / 32, BATCH);
        sink_fused_kernel<<<sgrid, 256>>>(lptr, rptr);
        sink_vpow_kernel<<<(BATCH * NSZ) / 256, 256>>>(lptr, rptr);
    }

    compute_P_kernel<<<BATCH * MSZ, 256>>>(tgt, Pout);
    cov_kernel<<<BATCH, 256>>>(src);
    svd_kernel<<<1, 32>>>(out);
}